// round 5
// baseline (speedup 1.0000x reference)
#include <cuda_runtime.h>

#define BB 2
#define CC 64
#define NN (64*64*64)          // 262144 tokens per batch
#define NHEADS 4
#define HID 128
#define EPSL 1e-5f
#define PBG 1024               // gram partial blocks per batch
#define TOKB (NN/PBG)          // 256 tokens per gram block

typedef unsigned long long u64;

// ---- scratch (device globals; no allocation) ----
__device__ float g_part[BB*PBG*CC*CC];   // 33.5 MB gram partials
__device__ float g_G[BB*CC*CC];          // gram matrices
__device__ float g_M[BB*HID*CC];         // per-head fold M [b][128][64]
__device__ float g_Pp[BB*CC*CC];         // P' stored k-major: [b][c][o]
__device__ float g_bp[BB*CC];            // b'

// ---- packed fp32x2 helpers (PTX-only; sm_100+) ----
__device__ __forceinline__ void ffma2(u64& d, u64 a, u64 b) {
    asm("fma.rn.f32x2 %0, %1, %2, %0;" : "+l"(d) : "l"(a), "l"(b));
}
__device__ __forceinline__ u64 pack2(float a, float b) {
    u64 r; asm("mov.b64 %0, {%1, %2};" : "=l"(r) : "f"(a), "f"(b)); return r;
}
__device__ __forceinline__ float2 unpack2(u64 v) {
    float2 r; asm("mov.b64 {%0, %1}, %2;" : "=f"(r.x), "=f"(r.y) : "l"(v)); return r;
}

// ============================================================
// Kernel 1: partial Gram  G[b] += X_chunk X_chunkT
// 64 threads (8x8 grid), 8x8 per-thread tile, interleaved row map
// (rows tr+8i / cols tc+8j), token-packed f32x2.
// ============================================================
__global__ void __launch_bounds__(64)
gram_kernel(const float* __restrict__ x) {
    const int b  = blockIdx.y;
    const int pb = blockIdx.x;
    const float* xb = x + (size_t)b * CC * NN + (size_t)pb * TOKB;

    __shared__ __align__(16) float xs[CC * 132];  // [c][t], 132-float rows (16B aligned, banks 4c)

    const int tid = threadIdx.x;       // 0..63
    const int tr  = tid & 7;
    const int tc  = tid >> 3;

    u64 acc2[8][8];
#pragma unroll
    for (int i = 0; i < 8; i++)
#pragma unroll
        for (int j = 0; j < 8; j++) acc2[i][j] = 0ull;

    for (int tile = 0; tile < TOKB; tile += 128) {
        __syncthreads();
        // 64 ch x 128 tokens = 2048 float4s, 32 per thread, coalesced
#pragma unroll
        for (int l = 0; l < 32; l++) {
            int idx = l * 64 + tid;
            int c   = idx >> 5;
            int t4  = (idx & 31) * 4;
            *(float4*)&xs[c * 132 + t4] = *(const float4*)(xb + (size_t)c * NN + tile + t4);
        }
        __syncthreads();

        for (int t = 0; t < 128; t += 4) {
            ulonglong2 av[8], bv[8];   // .x=(x[t],x[t+1]) .y=(x[t+2],x[t+3])
#pragma unroll
            for (int i = 0; i < 8; i++) av[i] = *(const ulonglong2*)&xs[(tr + 8 * i) * 132 + t];
#pragma unroll
            for (int j = 0; j < 8; j++) bv[j] = *(const ulonglong2*)&xs[(tc + 8 * j) * 132 + t];
#pragma unroll
            for (int i = 0; i < 8; i++)
#pragma unroll
                for (int j = 0; j < 8; j++) {
                    ffma2(acc2[i][j], av[i].x, bv[j].x);
                    ffma2(acc2[i][j], av[i].y, bv[j].y);
                }
        }
    }

    float* gp = g_part + (size_t)(b * PBG + pb) * CC * CC;
#pragma unroll
    for (int i = 0; i < 8; i++)
#pragma unroll
        for (int j = 0; j < 8; j++) {
            float2 p = unpack2(acc2[i][j]);
            gp[(tr + 8 * i) * CC + (tc + 8 * j)] = p.x + p.y;
        }
}

// ============================================================
// Kernel 2: reduce PBG partials -> G
// ============================================================
__global__ void __launch_bounds__(256)
gram_reduce() {
    const int b   = blockIdx.y;
    const int tid = threadIdx.x;
    const int el  = tid & 63;
    const int pq  = tid >> 6;
    const int e   = blockIdx.x * 64 + el;

    const float* base = g_part + (size_t)b * PBG * CC * CC + e;
    float s0 = 0.f, s1 = 0.f, s2 = 0.f, s3 = 0.f;
    for (int p = pq * 4; p < PBG; p += 16) {
        s0 += base[(size_t)(p + 0) * 4096];
        s1 += base[(size_t)(p + 1) * 4096];
        s2 += base[(size_t)(p + 2) * 4096];
        s3 += base[(size_t)(p + 3) * 4096];
    }
    __shared__ float red[256];
    red[tid] = s0 + s1 + s2 + s3;
    __syncthreads();
    if (pq == 0)
        g_G[b * 4096 + e] = red[el] + red[64 + el] + red[128 + el] + red[192 + el];
}

// ============================================================
// Kernel 3: per (head, batch):  M_h = scale * (Wk_h G Wv_h^T / 4096)^T Wq_h
// ============================================================
__global__ void __launch_bounds__(256)
computeM(const float* __restrict__ wqkv) {
    const int h = blockIdx.x, b = blockIdx.y, tid = threadIdx.x; // 256 threads
    __shared__ float Gs[4096];
    __shared__ float GV[2048];   // [r][e]
    __shared__ float Ws[2048];   // reused: Wv -> Wk -> Wq
    __shared__ float Cs[1024];   // [d][e]

    for (int i = tid; i < 4096; i += 256) Gs[i] = g_G[b * 4096 + i];
    for (int i = tid; i < 2048; i += 256) Ws[i] = wqkv[(256 + h * 32) * 64 + i]; // Wv_h
    __syncthreads();

    for (int i = tid; i < 2048; i += 256) {
        int r = i >> 5, e = i & 31;
        float s = 0.f;
#pragma unroll
        for (int c = 0; c < 64; c++) s += Gs[r * 64 + c] * Ws[e * 64 + c];
        GV[i] = s;
    }
    __syncthreads();

    for (int i = tid; i < 2048; i += 256) Ws[i] = wqkv[(128 + h * 32) * 64 + i]; // Wk_h
    __syncthreads();

    for (int i = tid; i < 1024; i += 256) {
        int d = i >> 5, e = i & 31;
        float s = 0.f;
#pragma unroll
        for (int r = 0; r < 64; r++) s += Ws[d * 64 + r] * GV[r * 32 + e];
        Cs[i] = s * (1.0f / 4096.0f);
    }
    __syncthreads();

    for (int i = tid; i < 2048; i += 256) Ws[i] = wqkv[(h * 32) * 64 + i]; // Wq_h
    __syncthreads();

    const float scale = 0.17677669529663687f;  // 32^-0.5
    for (int i = tid; i < 2048; i += 256) {
        int e = i >> 6, c = i & 63;
        float s = 0.f;
#pragma unroll
        for (int d = 0; d < 32; d++) s += Cs[d * 32 + e] * Ws[d * 64 + c];
        g_M[b * HID * 64 + (h * 32 + e) * 64 + c] = scale * s;
    }
}

// ============================================================
// Kernel 4: P' = w_out @ M - colmean(w_out) @ M, stored [c][o]
// ============================================================
__global__ void __launch_bounds__(256)
computeP(const float* __restrict__ wout, const float* __restrict__ bout) {
    const int b  = blockIdx.y;
    const int o0 = blockIdx.x * 16;
    const int tid = threadIdx.x;

    __shared__ float Ms[HID * 64];
    __shared__ float Wo[16 * HID];
    __shared__ float wbar[HID];
    __shared__ float colmu[64];

    for (int i = tid; i < HID * 64; i += 256)
        Ms[i] = g_M[b * HID * 64 + i];
    for (int i = tid; i < 16 * HID; i += 256)
        Wo[i] = wout[o0 * HID + i];
    if (tid < HID) {
        float s = 0.f;
#pragma unroll
        for (int o = 0; o < 64; o++) s += __ldg(&wout[o * HID + tid]);
        wbar[tid] = s * (1.0f / 64.0f);
    }
    __syncthreads();

    if (tid < 64) {
        float s = 0.f;
#pragma unroll 8
        for (int m = 0; m < HID; m++) s += wbar[m] * Ms[m * 64 + tid];
        colmu[tid] = s;
    }
    __syncthreads();

    for (int i = tid; i < 1024; i += 256) {
        int ol = i >> 6, c = i & 63;
        float s = 0.f;
#pragma unroll 8
        for (int m = 0; m < HID; m++) s += Wo[ol * HID + m] * Ms[m * 64 + c];
        g_Pp[b * 4096 + c * 64 + (o0 + ol)] = s - colmu[c];
    }

    if (blockIdx.x == 0 && tid < 64) {
        float s = 0.f;
        for (int o = 0; o < 64; o++) s += __ldg(&bout[o]);
        g_bp[b * 64 + tid] = __ldg(&bout[tid]) - s * (1.0f / 64.0f);
    }
}

// ============================================================
// Kernel 5: apply  y' = P' x + b'; out = y' * rsqrt(mean(y'^2)+eps) * g
// 64 ch x 256 tokens per block; x read directly from global (L1-served reuse);
// row-pair-packed f32x2; thread tile 8 rows x 8 tokens (4 + 4 at +128).
// ============================================================
__global__ void __launch_bounds__(256, 2)
apply_kernel(const float* __restrict__ x,
             const float* __restrict__ gg,
             float* __restrict__ out) {
    const int b  = blockIdx.y;
    const int n0 = blockIdx.x * 256;

    __shared__ __align__(16) float pk[4096];  // 16 KB [k][o]; reused for ssq/rs

    const int tid = threadIdx.x;
#pragma unroll
    for (int l = 0; l < 4; l++) {
        int idx = l * 256 + tid;
        *(float4*)&pk[idx * 4] = *(const float4*)(g_Pp + b * 4096 + idx * 4);
    }
    __syncthreads();

    const int tr = tid >> 5;            // 0..7
    const int r0 = tr * 8;
    const int t0 = (tid & 31) * 4;      // tokens t0..t0+3 and 128+t0..+3

    const float* xb = x + (size_t)b * CC * NN + n0;

    u64 acc2[4][8];                     // row pairs (r0+2i, r0+2i+1) x 8 tokens
#pragma unroll
    for (int i = 0; i < 4; i++)
#pragma unroll
        for (int j = 0; j < 8; j++) acc2[i][j] = 0ull;

#pragma unroll 4
    for (int k = 0; k < 64; k++) {
        ulonglong2 a01 = *(const ulonglong2*)&pk[k * 64 + r0];      // broadcast (warp-uniform)
        ulonglong2 a23 = *(const ulonglong2*)&pk[k * 64 + r0 + 4];
        float4 ba = *(const float4*)(xb + (size_t)k * NN + t0);
        float4 bb = *(const float4*)(xb + (size_t)k * NN + 128 + t0);
        u64 a2[4] = {a01.x, a01.y, a23.x, a23.y};
        u64 b2[8] = {pack2(ba.x, ba.x), pack2(ba.y, ba.y), pack2(ba.z, ba.z), pack2(ba.w, ba.w),
                     pack2(bb.x, bb.x), pack2(bb.y, bb.y), pack2(bb.z, bb.z), pack2(bb.w, bb.w)};
#pragma unroll
        for (int i = 0; i < 4; i++)
#pragma unroll
            for (int j = 0; j < 8; j++) ffma2(acc2[i][j], a2[i], b2[j]);
    }
    __syncthreads();   // pk dead -> reuse

    float acc[8][8];
#pragma unroll
    for (int i2 = 0; i2 < 4; i2++)
#pragma unroll
        for (int j = 0; j < 8; j++) {
            float2 p = unpack2(acc2[i2][j]);
            acc[2 * i2][j]     = p.x;
            acc[2 * i2 + 1][j] = p.y;
        }

    float* ssq_s = pk;            // [8][256]
    float* rs_s  = pk + 2048;     // [256]

    float ssq[8] = {0.f, 0.f, 0.f, 0.f, 0.f, 0.f, 0.f, 0.f};
#pragma unroll
    for (int i = 0; i < 8; i++) {
        float bpv = __ldg(&g_bp[b * 64 + r0 + i]);
#pragma unroll
        for (int j = 0; j < 8; j++) {
            float v = acc[i][j] + bpv;
            acc[i][j] = v;
            ssq[j] += v * v;
        }
    }
#pragma unroll
    for (int j = 0; j < 4; j++) ssq_s[tr * 256 + t0 + j] = ssq[j];
#pragma unroll
    for (int j = 0; j < 4; j++) ssq_s[tr * 256 + 128 + t0 + j] = ssq[4 + j];
    __syncthreads();

    {   // one token per thread
        float s = 0.f;
#pragma unroll
        for (int r = 0; r < 8; r++) s += ssq_s[r * 256 + tid];
        rs_s[tid] = rsqrtf(s * (1.0f / 64.0f) + EPSL);
    }
    __syncthreads();

    float rsa[4], rsb[4];
#pragma unroll
    for (int j = 0; j < 4; j++) { rsa[j] = rs_s[t0 + j]; rsb[j] = rs_s[128 + t0 + j]; }

    float* ob = out + (size_t)b * CC * NN + n0;
#pragma unroll
    for (int i = 0; i < 8; i++) {
        float gv = __ldg(&gg[r0 + i]);
        float4 o1, o2;
        o1.x = acc[i][0] * rsa[0] * gv;  o1.y = acc[i][1] * rsa[1] * gv;
        o1.z = acc[i][2] * rsa[2] * gv;  o1.w = acc[i][3] * rsa[3] * gv;
        o2.x = acc[i][4] * rsb[0] * gv;  o2.y = acc[i][5] * rsb[1] * gv;
        o2.z = acc[i][6] * rsb[2] * gv;  o2.w = acc[i][7] * rsb[3] * gv;
        *(float4*)(ob + (size_t)(r0 + i) * NN + t0)       = o1;
        *(float4*)(ob + (size_t)(r0 + i) * NN + 128 + t0) = o2;
    }
}

// ============================================================
extern "C" void kernel_launch(void* const* d_in, const int* in_sizes, int n_in,
                              void* d_out, int out_size) {
    const float* x    = (const float*)d_in[0];
    const float* wqkv = (const float*)d_in[1];
    const float* wout = (const float*)d_in[2];
    const float* bout = (const float*)d_in[3];
    const float* g    = (const float*)d_in[4];
    float* out = (float*)d_out;

    gram_kernel<<<dim3(PBG, BB), 64>>>(x);
    gram_reduce<<<dim3(64, BB), 256>>>();
    computeM<<<dim3(NHEADS, BB), 256>>>(wqkv);
    computeP<<<dim3(4, BB), 256>>>(wout, bout);
    apply_kernel<<<dim3(NN / 256, BB), 256>>>(x, g, out);
}